// round 5
// baseline (speedup 1.0000x reference)
#include <cuda_runtime.h>
#include <cuda_bf16.h>
#include <cstdint>

#define HID   2048
#define KSEL  256
#define NTOK  16384
#define NTHR  256
#define FULLW 0xFFFFFFFFu

__device__ int g_ids64;

// Detect int32 vs int64 ids (odd 32-bit words all zero => int64).
__global__ void detect_ids_kernel(const unsigned int* __restrict__ w) {
    __shared__ unsigned acc[NTHR];
    unsigned v = 0;
    for (int i = threadIdx.x; i < NTOK / 2; i += NTHR) v |= w[2 * i + 1];
    acc[threadIdx.x] = v;
    __syncthreads();
    for (int s = NTHR / 2; s > 0; s >>= 1) {
        if (threadIdx.x < s) acc[threadIdx.x] |= acc[threadIdx.x + s];
        __syncthreads();
    }
    if (threadIdx.x == 0) g_ids64 = (acc[0] == 0u) ? 1 : 0;
}

__device__ __forceinline__ unsigned f2key(float f) {
    unsigned u = __float_as_uint(f);
    return u ^ ((u & 0x80000000u) ? 0xFFFFFFFFu : 0x80000000u);
}
__device__ __forceinline__ float key2f(unsigned u) {
    unsigned b = (u & 0x80000000u) ? (u ^ 0x80000000u) : ~u;
    return __uint_as_float(b);
}

struct SmemT {
    unsigned ctr[2048];              // 8KB: histogram, then scatter counters
    unsigned cum[2048];              // 8KB: posBase[d] = # elements in bins > d
    unsigned long long sk[KSEL];     // 2KB: survivors (digit > bsel), bin-grouped
    unsigned long long cand[2048];   // 16KB: threshold-bin candidates
    unsigned warpTot[8];
    unsigned s_b, s_rem;
    unsigned cntN;
};

__global__ __launch_bounds__(NTHR, 6) void topk_kernel(
    const void* __restrict__ ids_raw,
    const float* __restrict__ W,
    float* __restrict__ out_val,
    float* __restrict__ out_idx)
{
    __shared__ SmemT s;
    const int tok  = blockIdx.x;
    const int tid  = threadIdx.x;
    const int lane = tid & 31;
    const int wrp  = tid >> 5;
    const unsigned ltm = (1u << lane) - 1u;

    if (tid == 0) s.cntN = 0u;

    // ---- gather one embedding row (coalesced float4) ----
    long long id;
    if (g_ids64) id = ((const long long*)ids_raw)[tok];
    else         id = (long long)((const int*)ids_raw)[tok];

    const float4* row = (const float4*)(W + (size_t)id * HID);
    float4 a = __ldg(row + tid);
    float4 b = __ldg(row + tid + NTHR);

    unsigned key[8];
    key[0] = f2key(a.x); key[1] = f2key(a.y); key[2] = f2key(a.z); key[3] = f2key(a.w);
    key[4] = f2key(b.x); key[5] = f2key(b.y); key[6] = f2key(b.z); key[7] = f2key(b.w);

    // ---- 11-bit histogram over the top bits ----
    uint4 z = make_uint4(0u, 0u, 0u, 0u);
    ((uint4*)s.ctr)[tid]        = z;
    ((uint4*)s.ctr)[tid + NTHR] = z;
    __syncthreads();

    #pragma unroll
    for (int e = 0; e < 8; e++)
        atomicAdd(&s.ctr[key[e] >> 21], 1u);
    __syncthreads();

    // ---- suffix scan: posBase per bin + locate threshold bin ----
    uint4 h0 = ((uint4*)s.ctr)[tid * 2];
    uint4 h1 = ((uint4*)s.ctr)[tid * 2 + 1];
    unsigned bins[8] = {h0.x, h0.y, h0.z, h0.w, h1.x, h1.y, h1.z, h1.w};
    unsigned tsum = 0;
    #pragma unroll
    for (int i = 0; i < 8; i++) tsum += bins[i];

    unsigned sfx = tsum;                        // sum over lanes >= mine
    #pragma unroll
    for (int off = 1; off < 32; off <<= 1) {
        unsigned y = __shfl_down_sync(FULLW, sfx, off);
        if (lane + off < 32) sfx += y;
    }
    if (lane == 0) s.warpTot[wrp] = sfx;
    __syncthreads();

    unsigned hiW = 0;
    #pragma unroll
    for (int w = 0; w < 8; w++) hiW += (w > wrp) ? s.warpTot[w] : 0u;

    unsigned run = hiW + (sfx - tsum);          // count in bins above my top bin
    unsigned pb[8];
    #pragma unroll
    for (int i = 7; i >= 0; i--) {
        unsigned h = bins[i];
        pb[i] = run;                            // posBase for bin tid*8+i
        if (run < KSEL && KSEL <= run + h) {
            s.s_b   = (unsigned)(tid * 8 + i);
            s.s_rem = KSEL - run;
        }
        run += h;
    }
    // Write posBase to cum (kept) and seed the scatter counters (ctr).
    uint4 p0 = make_uint4(pb[0], pb[1], pb[2], pb[3]);
    uint4 p1 = make_uint4(pb[4], pb[5], pb[6], pb[7]);
    ((uint4*)s.cum)[tid * 2]     = p0;
    ((uint4*)s.cum)[tid * 2 + 1] = p1;
    ((uint4*)s.ctr)[tid * 2]     = p0;
    ((uint4*)s.ctr)[tid * 2 + 1] = p1;
    __syncthreads();

    const unsigned bsel = s.s_b;
    const unsigned rem  = s.s_rem;              // 1..count(threshold bin)
    const int      nG   = (int)(KSEL - rem);    // survivors strictly above

    // ---- warp-aggregated scatter: digit>bsel -> sk segment, ==bsel -> cand ----
    #pragma unroll
    for (int e = 0; e < 8; e++) {
        unsigned k = key[e];
        unsigned d = k >> 21;
        int idx = (e < 4) ? (tid * 4 + e) : ((tid + NTHR) * 4 + (e - 4));
        unsigned long long comp = ((unsigned long long)k << 32) | (unsigned)(~idx);

        unsigned mask   = __match_any_sync(FULLW, d);
        unsigned leader = __ffs(mask) - 1u;
        unsigned base   = 0u;
        bool sel = (d >= bsel);
        unsigned* tgt = (d == bsel) ? &s.cntN : &s.ctr[d];
        if (lane == leader && sel) base = atomicAdd(tgt, __popc(mask));
        base = __shfl_sync(FULLW, base, leader);
        unsigned slot = base + __popc(mask & ltm);
        if (d > bsel)       s.sk[slot]   = comp;
        else if (d == bsel) s.cand[slot] = comp;
    }
    __syncthreads();

    const int n1 = (int)s.cntN;

    float* ov = out_val + (size_t)tok * KSEL;
    float* oi = out_idx + (size_t)tok * KSEL;

    // ---- survivors: rank within own tiny bin segment, write final slot ----
    if (tid < nG) {
        unsigned long long my = s.sk[tid];
        unsigned d  = (unsigned)(my >> 53);     // d > bsel >= 0  =>  d >= 1
        unsigned lo = s.cum[d];
        unsigned cnt = s.cum[d - 1] - lo;       // bin size
        int rank = 0;
        for (unsigned j = lo; j < lo + cnt; j++)
            rank += (s.sk[j] > my);
        ov[lo + rank] = key2f((unsigned)(my >> 32));
        oi[lo + rank] = (float)((int)(~(unsigned)my));
    }

    // ---- threshold-bin: exact rank-select top `rem`, slots [nG, 256) ----
    for (int t = tid; t < n1; t += NTHR) {
        unsigned long long my = s.cand[t];
        int rank = 0;
        for (int j = 0; j < n1; j++) rank += (s.cand[j] > my);
        if (rank < (int)rem) {
            ov[nG + rank] = key2f((unsigned)(my >> 32));
            oi[nG + rank] = (float)((int)(~(unsigned)my));
        }
    }
}

extern "C" void kernel_launch(void* const* d_in, const int* in_sizes, int n_in,
                              void* d_out, int out_size)
{
    const void*  ids = d_in[0];
    const float* W   = (const float*)d_in[1];

    float* out_val = (float*)d_out;
    float* out_idx = (float*)d_out + (size_t)NTOK * KSEL;

    detect_ids_kernel<<<1, NTHR>>>((const unsigned int*)ids);
    topk_kernel<<<NTOK, NTHR>>>(ids, W, out_val, out_idx);
}

// round 6
// speedup vs baseline: 1.0589x; 1.0589x over previous
#include <cuda_runtime.h>
#include <cuda_bf16.h>
#include <cstdint>

#define HID   2048
#define KSEL  256
#define NTOK  16384
#define NTHR  256
#define FULLW 0xFFFFFFFFu

__device__ int g_ids64;

// Phase A: assume int64. Phase B: any nonzero odd 32-bit word => int32.
__global__ void detect_init_kernel() { g_ids64 = 1; }

__global__ void detect_ids_kernel(const unsigned int* __restrict__ w) {
    unsigned v = 0;
    for (int i = blockIdx.x * blockDim.x + threadIdx.x; i < NTOK / 2;
         i += gridDim.x * blockDim.x)
        v |= w[2 * i + 1];
    if (v) g_ids64 = 0;     // benign race: all writers store 0
}

__device__ __forceinline__ unsigned f2key(float f) {
    unsigned u = __float_as_uint(f);
    return u ^ ((u & 0x80000000u) ? 0xFFFFFFFFu : 0x80000000u);
}
__device__ __forceinline__ float key2f(unsigned u) {
    unsigned b = (u & 0x80000000u) ? (u ^ 0x80000000u) : ~u;
    return __uint_as_float(b);
}

struct SmemT {
    unsigned hist[2048];             // 8KB
    unsigned long long sk[KSEL];     // 2KB: final 256 composite keys
    unsigned long long cand[2048];   // 16KB: threshold-bucket candidates
    unsigned warpTot[8];
    unsigned s_b, s_rem;
    int cntG, cntN;
};

__global__ __launch_bounds__(NTHR, 7) void topk_kernel(
    const void* __restrict__ ids_raw,
    const float* __restrict__ W,
    float* __restrict__ out_val,
    float* __restrict__ out_idx)
{
    __shared__ SmemT s;
    const int tok  = blockIdx.x;
    const int tid  = threadIdx.x;
    const int lane = tid & 31;
    const int wrp  = tid >> 5;
    const unsigned ltm = (1u << lane) - 1u;

    if (tid == 0) { s.cntG = 0; s.cntN = 0; }

    // ---- gather one embedding row (coalesced float4) ----
    long long id;
    if (g_ids64) id = ((const long long*)ids_raw)[tok];
    else         id = (long long)((const int*)ids_raw)[tok];

    const float4* row = (const float4*)(W + (size_t)id * HID);
    float4 a = __ldg(row + tid);
    float4 b = __ldg(row + tid + NTHR);

    unsigned key[8];
    key[0] = f2key(a.x); key[1] = f2key(a.y); key[2] = f2key(a.z); key[3] = f2key(a.w);
    key[4] = f2key(b.x); key[5] = f2key(b.y); key[6] = f2key(b.z); key[7] = f2key(b.w);

    // ---- single 11-bit radix pass, match-aggregated atomics ----
    uint4 z = make_uint4(0u, 0u, 0u, 0u);
    ((uint4*)s.hist)[tid]        = z;
    ((uint4*)s.hist)[tid + NTHR] = z;
    __syncthreads();

    #pragma unroll
    for (int e = 0; e < 8; e++) {
        unsigned d = key[e] >> 21;
        unsigned mask = __match_any_sync(FULLW, d);
        if (lane == (unsigned)(__ffs(mask) - 1))
            atomicAdd(&s.hist[d], (unsigned)__popc(mask));
    }
    __syncthreads();

    // ---- parallel suffix scan to locate the threshold bucket ----
    uint4 h0 = ((uint4*)s.hist)[tid * 2];
    uint4 h1 = ((uint4*)s.hist)[tid * 2 + 1];
    unsigned bins[8] = {h0.x, h0.y, h0.z, h0.w, h1.x, h1.y, h1.z, h1.w};
    unsigned tsum = 0;
    #pragma unroll
    for (int i = 0; i < 8; i++) tsum += bins[i];

    unsigned sfx = tsum;                           // sum over lanes >= mine
    #pragma unroll
    for (int off = 1; off < 32; off <<= 1) {
        unsigned y = __shfl_down_sync(FULLW, sfx, off);
        if (lane + off < 32) sfx += y;
    }
    if (lane == 0) s.warpTot[wrp] = sfx;
    __syncthreads();

    unsigned hiW = 0;
    #pragma unroll
    for (int w = 0; w < 8; w++) hiW += (w > wrp) ? s.warpTot[w] : 0u;

    unsigned run = hiW + (sfx - tsum);             // count in bins above my top bin
    #pragma unroll
    for (int i = 7; i >= 0; i--) {
        unsigned h = bins[i];
        if (run < KSEL && KSEL <= run + h) {
            s.s_b   = (unsigned)(tid * 8 + i);
            s.s_rem = KSEL - run;
        }
        run += h;
    }
    __syncthreads();

    const unsigned bsel = s.s_b;
    const unsigned rem  = s.s_rem;                 // 1..count(bucket)

    // ---- ballot-aggregated compaction: >bucket to sk, ==bucket to cand ----
    #pragma unroll
    for (int e = 0; e < 8; e++) {
        unsigned k = key[e];
        unsigned d = k >> 21;
        int idx = (e < 4) ? (tid * 4 + e) : ((tid + NTHR) * 4 + (e - 4));
        bool g = (d > bsel), q = (d == bsel);
        unsigned mg = __ballot_sync(FULLW, g);
        unsigned mq = __ballot_sync(FULLW, q);
        int baseG = 0, baseN = 0;
        if (lane == 0) {
            if (mg) baseG = atomicAdd(&s.cntG, __popc(mg));
            if (mq) baseN = atomicAdd(&s.cntN, __popc(mq));
        }
        baseG = __shfl_sync(FULLW, baseG, 0);
        baseN = __shfl_sync(FULLW, baseN, 0);
        unsigned long long comp = ((unsigned long long)k << 32) | (unsigned)(~idx);
        if (g) s.sk[baseG + __popc(mg & ltm)]   = comp;
        if (q) s.cand[baseN + __popc(mq & ltm)] = comp;
    }
    __syncthreads();

    const int nG = s.cntG;     // == KSEL - rem
    const int n1 = s.cntN;     // typically ~25-90; up to 2048 worst case

    // ---- exact rank-select the top `rem` candidates by composite key ----
    for (int t = tid; t < n1; t += NTHR) {
        unsigned long long my = s.cand[t];
        int rank = 0;
        for (int j = 0; j < n1; j++) rank += (s.cand[j] > my);
        if (rank < (int)rem) s.sk[nG + rank] = my;
    }
    __syncthreads();

    // ---- bitonic sort of 256 distinct composite keys, descending ----
    unsigned long long v = s.sk[tid];

    #pragma unroll
    for (int kk = 2; kk <= 32; kk <<= 1) {
        #pragma unroll
        for (int j = kk >> 1; j >= 1; j >>= 1) {
            bool keepL = ((tid & j) == 0) != ((tid & kk) != 0);
            unsigned long long o = __shfl_xor_sync(FULLW, v, j);
            v = ((o > v) == keepL) ? o : v;
        }
    }
    #pragma unroll
    for (int kk = 64; kk <= 256; kk <<= 1) {
        #pragma unroll
        for (int j = kk >> 1; j >= 32; j >>= 1) {
            s.sk[tid] = v;
            __syncthreads();
            unsigned long long o = s.sk[tid ^ j];
            bool keepL = ((tid & j) == 0) != ((tid & kk) != 0);
            v = ((o > v) == keepL) ? o : v;
            __syncthreads();
        }
        #pragma unroll
        for (int j = 16; j >= 1; j >>= 1) {
            bool keepL = ((tid & j) == 0) != ((tid & kk) != 0);
            unsigned long long o = __shfl_xor_sync(FULLW, v, j);
            v = ((o > v) == keepL) ? o : v;
        }
    }

    float* ov = out_val + (size_t)tok * KSEL;
    float* oi = out_idx + (size_t)tok * KSEL;
    ov[tid] = key2f((unsigned)(v >> 32));
    oi[tid] = (float)((int)(~(unsigned)v));
}

extern "C" void kernel_launch(void* const* d_in, const int* in_sizes, int n_in,
                              void* d_out, int out_size)
{
    const void*  ids = d_in[0];
    const float* W   = (const float*)d_in[1];

    float* out_val = (float*)d_out;
    float* out_idx = (float*)d_out + (size_t)NTOK * KSEL;

    detect_init_kernel<<<1, 1>>>();
    detect_ids_kernel<<<16, NTHR>>>((const unsigned int*)ids);
    topk_kernel<<<NTOK, NTHR>>>(ids, W, out_val, out_idx);
}

// round 7
// speedup vs baseline: 1.3148x; 1.2416x over previous
#include <cuda_runtime.h>
#include <cuda_bf16.h>
#include <cstdint>

#define HID   2048
#define KSEL  256
#define NTOK  16384
#define NTHR  256
#define FULLW 0xFFFFFFFFu

__device__ int g_ids64;

// Detect int32 vs int64 ids (odd 32-bit words all zero => int64).
__global__ void detect_ids_kernel(const unsigned int* __restrict__ w) {
    __shared__ unsigned acc[NTHR];
    unsigned v = 0;
    for (int i = threadIdx.x; i < NTOK / 2; i += NTHR) v |= w[2 * i + 1];
    acc[threadIdx.x] = v;
    __syncthreads();
    for (int s = NTHR / 2; s > 0; s >>= 1) {
        if (threadIdx.x < s) acc[threadIdx.x] |= acc[threadIdx.x + s];
        __syncthreads();
    }
    if (threadIdx.x == 0) g_ids64 = (acc[0] == 0u) ? 1 : 0;
}

__device__ __forceinline__ unsigned f2key(float f) {
    unsigned u = __float_as_uint(f);
    return u ^ ((u & 0x80000000u) ? 0xFFFFFFFFu : 0x80000000u);
}
__device__ __forceinline__ float key2f(unsigned u) {
    unsigned b = (u & 0x80000000u) ? (u ^ 0x80000000u) : ~u;
    return __uint_as_float(b);
}

struct SmemT {
    unsigned ctr[2048];              // 8KB: histogram, then scatter counters
    unsigned cum[2048];              // 8KB: posBase[d] = # elements in bins > d
    unsigned long long sk[KSEL];     // 2KB: survivors grouped by bin segment
    unsigned long long cand[2048];   // 16KB: threshold-bin candidates
    float outV[KSEL];                // 1KB: staged final values
    float outI[KSEL];                // 1KB: staged final indices (as float)
    unsigned warpTot[8];
    unsigned s_b, s_rem;
    unsigned cntN;
};

__global__ __launch_bounds__(NTHR, 6) void topk_kernel(
    const void* __restrict__ ids_raw,
    const float* __restrict__ W,
    float* __restrict__ out_val,
    float* __restrict__ out_idx)
{
    __shared__ SmemT s;
    const int tok  = blockIdx.x;
    const int tid  = threadIdx.x;
    const int lane = tid & 31;
    const int wrp  = tid >> 5;

    if (tid == 0) s.cntN = 0u;

    // ---- gather one embedding row (coalesced float4) ----
    long long id;
    if (g_ids64) id = ((const long long*)ids_raw)[tok];
    else         id = (long long)((const int*)ids_raw)[tok];

    const float4* row = (const float4*)(W + (size_t)id * HID);
    float4 a = __ldg(row + tid);
    float4 b = __ldg(row + tid + NTHR);

    unsigned key[8];
    key[0] = f2key(a.x); key[1] = f2key(a.y); key[2] = f2key(a.z); key[3] = f2key(a.w);
    key[4] = f2key(b.x); key[5] = f2key(b.y); key[6] = f2key(b.z); key[7] = f2key(b.w);

    // ---- 11-bit histogram over the top bits (plain atomics, proven best) ----
    uint4 z = make_uint4(0u, 0u, 0u, 0u);
    ((uint4*)s.ctr)[tid]        = z;
    ((uint4*)s.ctr)[tid + NTHR] = z;
    __syncthreads();

    #pragma unroll
    for (int e = 0; e < 8; e++)
        atomicAdd(&s.ctr[key[e] >> 21], 1u);
    __syncthreads();

    // ---- suffix scan: posBase per bin + locate threshold bin ----
    uint4 h0 = ((uint4*)s.ctr)[tid * 2];
    uint4 h1 = ((uint4*)s.ctr)[tid * 2 + 1];
    unsigned bins[8] = {h0.x, h0.y, h0.z, h0.w, h1.x, h1.y, h1.z, h1.w};
    unsigned tsum = 0;
    #pragma unroll
    for (int i = 0; i < 8; i++) tsum += bins[i];

    unsigned sfx = tsum;                        // sum over lanes >= mine
    #pragma unroll
    for (int off = 1; off < 32; off <<= 1) {
        unsigned y = __shfl_down_sync(FULLW, sfx, off);
        if (lane + off < 32) sfx += y;
    }
    if (lane == 0) s.warpTot[wrp] = sfx;
    __syncthreads();

    unsigned hiW = 0;
    #pragma unroll
    for (int w = 0; w < 8; w++) hiW += (w > wrp) ? s.warpTot[w] : 0u;

    unsigned run = hiW + (sfx - tsum);          // count in bins above my top bin
    unsigned pb[8];
    #pragma unroll
    for (int i = 7; i >= 0; i--) {
        unsigned h = bins[i];
        pb[i] = run;                            // posBase for bin tid*8+i
        if (run < KSEL && KSEL <= run + h) {
            s.s_b   = (unsigned)(tid * 8 + i);
            s.s_rem = KSEL - run;
        }
        run += h;
    }
    // posBase to cum (kept for rank lookups) and seed scatter counters (ctr).
    uint4 p0 = make_uint4(pb[0], pb[1], pb[2], pb[3]);
    uint4 p1 = make_uint4(pb[4], pb[5], pb[6], pb[7]);
    ((uint4*)s.cum)[tid * 2]     = p0;
    ((uint4*)s.cum)[tid * 2 + 1] = p1;
    ((uint4*)s.ctr)[tid * 2]     = p0;
    ((uint4*)s.ctr)[tid * 2 + 1] = p1;
    __syncthreads();

    const unsigned bsel = s.s_b;
    const unsigned rem  = s.s_rem;              // 1..count(threshold bin)
    const int      nG   = (int)(KSEL - rem);    // survivors strictly above

    // ---- scatter: only ~256+n1 of 2048 elements do an atomic ----
    #pragma unroll
    for (int e = 0; e < 8; e++) {
        unsigned k = key[e];
        unsigned d = k >> 21;
        if (d < bsel) continue;
        int idx = (e < 4) ? (tid * 4 + e) : ((tid + NTHR) * 4 + (e - 4));
        unsigned long long comp = ((unsigned long long)k << 32) | (unsigned)(~idx);
        if (d > bsel) {
            unsigned slot = atomicAdd(&s.ctr[d], 1u);   // within-bin contention ~3
            s.sk[slot] = comp;
        } else {
            unsigned slot = atomicAdd(&s.cntN, 1u);
            s.cand[slot] = comp;
        }
    }
    __syncthreads();

    const int n1 = (int)s.cntN;

    // ---- survivors: rank within own tiny bin segment (staged in smem) ----
    if (tid < nG) {
        unsigned long long my = s.sk[tid];
        unsigned d   = (unsigned)(my >> 53);    // d > bsel >= 0  =>  d >= 1
        unsigned lo  = s.cum[d];
        unsigned hi  = s.cum[d - 1];            // lo + bin size
        int rank = 0;
        for (unsigned j = lo; j < hi; j++)
            rank += (s.sk[j] > my);
        s.outV[lo + rank] = key2f((unsigned)(my >> 32));
        s.outI[lo + rank] = (float)((int)(~(unsigned)my));
    }

    // ---- threshold bin: exact rank-select top `rem` into slots [nG, 256) ----
    for (int t = tid; t < n1; t += NTHR) {
        unsigned long long my = s.cand[t];
        int rank = 0;
        for (int j = 0; j < n1; j++) rank += (s.cand[j] > my);
        if (rank < (int)rem) {
            s.outV[nG + rank] = key2f((unsigned)(my >> 32));
            s.outI[nG + rank] = (float)((int)(~(unsigned)my));
        }
    }
    __syncthreads();

    // ---- single fully-coalesced global write ----
    float* ov = out_val + (size_t)tok * KSEL;
    float* oi = out_idx + (size_t)tok * KSEL;
    ov[tid] = s.outV[tid];
    oi[tid] = s.outI[tid];
}

extern "C" void kernel_launch(void* const* d_in, const int* in_sizes, int n_in,
                              void* d_out, int out_size)
{
    const void*  ids = d_in[0];
    const float* W   = (const float*)d_in[1];

    float* out_val = (float*)d_out;
    float* out_idx = (float*)d_out + (size_t)NTOK * KSEL;

    detect_ids_kernel<<<1, NTHR>>>((const unsigned int*)ids);
    topk_kernel<<<NTOK, NTHR>>>(ids, W, out_val, out_idx);
}